// round 1
// baseline (speedup 1.0000x reference)
#include <cuda_runtime.h>

#define NB     2048
#define NOH    20
#define NOTH   23
#define NC     10
#define SC     200      // NOH*NC
#define EMB    9
#define OUTC   32
#define XSTR   43       // NOH + NOTH
#define HW     2304     // 48*48
#define SLABSZ 73728    // OUTC*HW floats per unique slab

// Scratch (device globals: allocation-free per harness rules)
__device__ float g_v[NB * EMB];          // per-batch embedding vector
__device__ float g_Wc[OUTC * 32];        // fused 32x32 weight [o][k], k<9 = v-part, k>=9 = others-part
__device__ float g_cb[OUTC];             // fused bias
__device__ float g_slab[8 * SLABSZ];     // the 8 unique output slabs (2.36 MB)

// ---------------------------------------------------------------------------
// k0: fold the three 1x1 convs into one 32x32 weight + bias. 1 block, 32 thr.
__global__ void k_weights(const float* __restrict__ oh_w, const float* __restrict__ oh_b,
                          const float* __restrict__ ot_w, const float* __restrict__ ot_b,
                          const float* __restrict__ all_w, const float* __restrict__ all_b) {
    int o = threadIdx.x;               // 0..31
    float cb = all_b[o];
    // v-part: W1[o,i] = sum_c all_w[o,c] * oh_w[c,i], c<9
    for (int i = 0; i < EMB; i++) {
        float s = 0.f;
        for (int c = 0; c < EMB; c++) s += all_w[o * 32 + c] * oh_w[c * EMB + i];
        g_Wc[o * 32 + i] = s;
    }
    for (int c = 0; c < EMB; c++) cb += all_w[o * 32 + c] * oh_b[c];
    // others-part: W2[o,j] = sum_c all_w[o,9+c] * ot_w[c,j], c<23
    for (int j = 0; j < NOTH; j++) {
        float s = 0.f;
        for (int c = 0; c < NOTH; c++) s += all_w[o * 32 + EMB + c] * ot_w[c * NOTH + j];
        g_Wc[o * 32 + EMB + j] = s;
    }
    for (int c = 0; c < NOTH; c++) cb += all_w[o * 32 + EMB + c] * ot_b[c];
    g_cb[o] = cb;
}

// ---------------------------------------------------------------------------
// k1: v[b,e] = fc_b[e] + sum_j fc_w[e, 10*j + idx[b,j]].  16 blocks x 128 thr.
__global__ void k_embed(const float* __restrict__ x,
                        const float* __restrict__ fc_w,
                        const float* __restrict__ fc_b) {
    __shared__ float sw[EMB * SC];     // 7.2 KB
    int t = threadIdx.x;
    for (int i = t; i < EMB * SC; i += 128) sw[i] = fc_w[i];
    __syncthreads();

    int b = blockIdx.x * 128 + t;
    float acc[EMB];
#pragma unroll
    for (int e = 0; e < EMB; e++) acc[e] = fc_b[e];
    const float* xb = x + b * XSTR;
#pragma unroll 4
    for (int j = 0; j < NOH; j++) {
        int idx = (int)xb[j];          // exact small integer stored as float
        int base = j * NC + idx;
#pragma unroll
        for (int e = 0; e < EMB; e++) acc[e] += sw[e * SC + base];
    }
#pragma unroll
    for (int e = 0; e < EMB; e++) g_v[b * EMB + e] = acc[e];
}

// ---------------------------------------------------------------------------
// k2: compute the 8 unique slabs.
// slab[c][o][m] = cb[o] + sum_i W[o,i]*v[256*((c+i)&7)+q, r]
//                       + sum_j W[o,9+j]*x[bb_o*43 + 20 + (4j+m)%23]
// where q=m/9, r=m%9, bb_o = (256c + (2304j+m)/23) & 2047.
// grid = 8*18 blocks x 128 thr (one thread per (c,m)).
__global__ void k_slab(const float* __restrict__ x) {
    __shared__ float sW[OUTC * 32];
    __shared__ float scb[OUTC];
    int t = threadIdx.x;
    for (int i = t; i < OUTC * 32; i += 128) sW[i] = g_Wc[i];
    if (t < OUTC) scb[t] = g_cb[t];
    __syncthreads();

    int bid = blockIdx.x;
    int c = bid / 18;                  // 0..7
    int m = (bid % 18) * 128 + t;      // 0..2303
    int q = m / 9;
    int r = m - 9 * q;

    float g[32];
#pragma unroll
    for (int i = 0; i < 9; i++)
        g[i] = g_v[(256 * ((c + i) & 7) + q) * EMB + r];
#pragma unroll
    for (int j = 0; j < 23; j++) {
        int eo = (4 * j + m) % 23;
        int T  = (2304 * j + m) / 23;
        int bb = (256 * c + T) & 2047;
        g[9 + j] = x[bb * XSTR + NOH + eo];
    }

    float* dst = g_slab + c * SLABSZ + m;
#pragma unroll
    for (int o = 0; o < OUTC; o++) {
        float s = scb[o];
#pragma unroll
        for (int k = 0; k < 32; k++) s += sW[o * 32 + k] * g[k];
        dst[o * HW] = s;
    }
}

// ---------------------------------------------------------------------------
// k3: replicate: out[b][.] = slab[b%8][.], 604 MB of pure stores.
// Each CTA stages an 8192-float (32 KB) chunk in registers (read once from L2),
// then stores it for 32 batch indices sharing c = b%8.
// grid = 8 c * 9 chunks * 8 bgroups = 576 CTAs, 256 threads.
__global__ void __launch_bounds__(256) k_replicate(float* __restrict__ out) {
    int bid = blockIdx.x;
    int c     = bid / 72;              // 0..7
    int rest  = bid % 72;
    int chunk = rest / 8;              // 0..8
    int bg    = rest % 8;              // 0..7
    int t = threadIdx.x;

    size_t chunk_off = (size_t)chunk * 8192;
    const float4* __restrict__ src =
        (const float4*)(g_slab + (size_t)c * SLABSZ + chunk_off);

    float4 r0 = src[0 * 256 + t];
    float4 r1 = src[1 * 256 + t];
    float4 r2 = src[2 * 256 + t];
    float4 r3 = src[3 * 256 + t];
    float4 r4 = src[4 * 256 + t];
    float4 r5 = src[5 * 256 + t];
    float4 r6 = src[6 * 256 + t];
    float4 r7 = src[7 * 256 + t];

#pragma unroll 4
    for (int u = 0; u < 32; u++) {
        int b = c + 8 * (bg * 32 + u);
        float4* __restrict__ dst = (float4*)(out + (size_t)b * SLABSZ + chunk_off);
        dst[0 * 256 + t] = r0;
        dst[1 * 256 + t] = r1;
        dst[2 * 256 + t] = r2;
        dst[3 * 256 + t] = r3;
        dst[4 * 256 + t] = r4;
        dst[5 * 256 + t] = r5;
        dst[6 * 256 + t] = r6;
        dst[7 * 256 + t] = r7;
    }
}

// ---------------------------------------------------------------------------
extern "C" void kernel_launch(void* const* d_in, const int* in_sizes, int n_in,
                              void* d_out, int out_size) {
    const float* x     = (const float*)d_in[0];
    const float* fc_w  = (const float*)d_in[1];
    const float* fc_b  = (const float*)d_in[2];
    const float* oh_w  = (const float*)d_in[3];
    const float* oh_b  = (const float*)d_in[4];
    const float* ot_w  = (const float*)d_in[5];
    const float* ot_b  = (const float*)d_in[6];
    const float* all_w = (const float*)d_in[7];
    const float* all_b = (const float*)d_in[8];
    float* out = (float*)d_out;

    k_weights<<<1, 32>>>(oh_w, oh_b, ot_w, ot_b, all_w, all_b);
    k_embed<<<NB / 128, 128>>>(x, fc_w, fc_b);
    k_slab<<<8 * 18, 128>>>(x);
    k_replicate<<<576, 256>>>(out);
}